// round 3
// baseline (speedup 1.0000x reference)
#include <cuda_runtime.h>
#include <cuda_bf16.h>
#include <cstdint>

// Problem constants (fixed by setup_inputs)
#define BATCH 4
#define MDIM 4096
#define NDIM 32
#define CDIM 256
#define DDIM 128
#define ROWS (BATCH * MDIM)        // 16384
#define RB 16                      // rows per block in fused kernel
#define LN_EPS 1e-5f
#define SCALE 0.08838834764831845f // 1/sqrt(128)

// ---------------- scratch (device globals, no allocation) ----------------
__device__ __align__(16) float g_M2[CDIM * CDIM]; // (Wq Wk^T)[c][c'] * k_gamma[c']
__device__ __align__(16) float g_bv2[CDIM];       // k_gamma[c'] * (Wk[c',:]·bq)
__device__ __align__(16) float g_rowvec[CDIM];    // mb[c] + u[c]
__device__ float g_const[1];                      // k_beta·bv + bq·bk
__device__ __align__(16) float g_e[CDIM];         // q_gamma ⊙ rowvec
__device__ float g_EF[2];                         // {E = Σe, F + const}

// ---------------- helpers ----------------
__device__ __forceinline__ float blockSum256(float v, float* s8) {
    #pragma unroll
    for (int o = 16; o; o >>= 1) v += __shfl_xor_sync(0xffffffffu, v, o);
    __syncthreads();
    if ((threadIdx.x & 31) == 0) s8[threadIdx.x >> 5] = v;
    __syncthreads();
    float tot = 0.f;
    #pragma unroll
    for (int i = 0; i < 8; i++) tot += s8[i];
    return tot;
}

#define FMA2(d, a, b) \
    asm("fma.rn.f32x2 %0, %1, %2, %0;" : "+l"(d) : "l"(a), "l"(b))
#define PACK2(out, lo, hi) \
    asm("mov.b64 %0, {%1, %2};" : "=l"(out) : "r"(__float_as_uint(lo)), "r"(__float_as_uint(hi)))

__device__ __forceinline__ float2 unpack2(unsigned long long v) {
    unsigned int lo, hi;
    asm("mov.b64 {%0, %1}, %2;" : "=r"(lo), "=r"(hi) : "l"(v));
    return make_float2(__uint_as_float(lo), __uint_as_float(hi));
}

// ---------------- K1: prep M2, bv2, rowvec, const ----------------
__global__ void prep_kernel(const float* __restrict__ Wq, const float* __restrict__ Wk,
                            const float* __restrict__ bq, const float* __restrict__ bk,
                            const float* __restrict__ kg, const float* __restrict__ kb) {
    int c = blockIdx.x;            // 0..255
    int t = threadIdx.x;           // 0..255  (t == c')
    __shared__ float sq[DDIM];
    __shared__ float s8[8];
    if (t < DDIM) sq[t] = Wq[c * DDIM + t];
    __syncthreads();

    const float* wkr = Wk + t * DDIM;
    float acc = 0.f;
    #pragma unroll 4
    for (int d = 0; d < DDIM; d++) acc += sq[d] * wkr[d];

    g_M2[c * CDIM + t] = acc * kg[t];

    float mb = blockSum256(acc * kb[t], s8);
    if (t == 0) {
        float u = 0.f;
        #pragma unroll 4
        for (int d = 0; d < DDIM; d++) u += Wq[c * DDIM + d] * bk[d];
        g_rowvec[c] = mb + u;
    }

    if (c == 0) {
        float bv = 0.f;
        #pragma unroll 4
        for (int d = 0; d < DDIM; d++) bv += wkr[d] * bq[d];
        g_bv2[t] = bv * kg[t];
        float cb = blockSum256(bv * kb[t], s8);
        if (t == 0) {
            float bb = 0.f;
            #pragma unroll 4
            for (int d = 0; d < DDIM; d++) bb += bq[d] * bk[d];
            g_const[0] = cb + bb;
        }
    }
}

// ---------------- K1b: e = qg*rowvec, E, F ----------------
__global__ void prep2_kernel(const float* __restrict__ qg, const float* __restrict__ qb) {
    int t = threadIdx.x;
    __shared__ float s8[8];
    float rv = g_rowvec[t];
    float e = qg[t] * rv;
    g_e[t] = e;
    float E = blockSum256(e, s8);
    float F = blockSum256(qb[t] * rv, s8);
    if (t == 0) { g_EF[0] = E; g_EF[1] = F + g_const[0]; }
}

// ---------------- K2: FUSED stats + matvec + attention ----------------
// One block = 16 rows. Phase A: LN stats + Bc. Phase B: w = LN(x) @ M2 + bv2
// (f32x2 packed FMAs, M2 streamed from L2). Phase C: stream y, softmax, z-sum.
__global__ void __launch_bounds__(256, 4)
fused_kernel(const float* __restrict__ x, const float* __restrict__ y,
             const float* __restrict__ z, const float* __restrict__ qg,
             const float* __restrict__ qb, float* __restrict__ out) {
    __shared__ __align__(16) float s_lnx[RB][CDIM];   // 16KB normalized x rows
    __shared__ __align__(16) float s_w[RB][CDIM];     // 16KB per-row weight vectors
    __shared__ __align__(16) float s_e[CDIM];
    __shared__ __align__(16) float s_g[CDIM];
    __shared__ __align__(16) float s_b[CDIM];
    __shared__ float s_bc[RB], s_G[RB];
    __shared__ float s_dot[2][NDIM];
    __shared__ float s_EF[2];

    const int tid = threadIdx.x;
    const int row0 = blockIdx.x * RB;

    s_e[tid] = g_e[tid];
    s_g[tid] = qg[tid];
    s_b[tid] = qb[tid];
    if (tid < 2) s_EF[tid] = g_EF[tid];
    __syncthreads();

    // ---------- Phase A: stats + LN + Bc (warp w -> rows 2w, 2w+1) ----------
    {
        const int wi = tid >> 5, l = tid & 31;
        #pragma unroll
        for (int rr = 0; rr < 2; rr++) {
            const int r = wi * 2 + rr;
            const float* xr = x + (size_t)(row0 + r) * CDIM;
            const int ka = l * 4, kb2 = 128 + l * 4;
            float4 xa = *(const float4*)(xr + ka);
            float4 xb = *(const float4*)(xr + kb2);
            float s1 = xa.x + xa.y + xa.z + xa.w + xb.x + xb.y + xb.z + xb.w;
            float s2 = xa.x*xa.x + xa.y*xa.y + xa.z*xa.z + xa.w*xa.w
                     + xb.x*xb.x + xb.y*xb.y + xb.z*xb.z + xb.w*xb.w;
            float s3 = xa.x*s_e[ka] + xa.y*s_e[ka+1] + xa.z*s_e[ka+2] + xa.w*s_e[ka+3]
                     + xb.x*s_e[kb2] + xb.y*s_e[kb2+1] + xb.z*s_e[kb2+2] + xb.w*s_e[kb2+3];
            #pragma unroll
            for (int o = 16; o; o >>= 1) {
                s1 += __shfl_xor_sync(0xffffffffu, s1, o);
                s2 += __shfl_xor_sync(0xffffffffu, s2, o);
                s3 += __shfl_xor_sync(0xffffffffu, s3, o);
            }
            float mu = s1 * (1.f / CDIM);
            float var = s2 * (1.f / CDIM) - mu * mu;
            float rs = rsqrtf(var + LN_EPS);
            if (l == 0) s_bc[r] = rs * (s3 - mu * s_EF[0]) + s_EF[1];
            s_lnx[r][ka+0] = (xa.x - mu) * rs * s_g[ka+0] + s_b[ka+0];
            s_lnx[r][ka+1] = (xa.y - mu) * rs * s_g[ka+1] + s_b[ka+1];
            s_lnx[r][ka+2] = (xa.z - mu) * rs * s_g[ka+2] + s_b[ka+2];
            s_lnx[r][ka+3] = (xa.w - mu) * rs * s_g[ka+3] + s_b[ka+3];
            s_lnx[r][kb2+0] = (xb.x - mu) * rs * s_g[kb2+0] + s_b[kb2+0];
            s_lnx[r][kb2+1] = (xb.y - mu) * rs * s_g[kb2+1] + s_b[kb2+1];
            s_lnx[r][kb2+2] = (xb.z - mu) * rs * s_g[kb2+2] + s_b[kb2+2];
            s_lnx[r][kb2+3] = (xb.w - mu) * rs * s_g[kb2+3] + s_b[kb2+3];
        }
    }
    __syncthreads();

    // ---------- Phase B: w[r][c] = sum_k lnx[r][k]*M2[k][c] + bv2[c] ----------
    // thread (r = tid>>4, jc = tid&15) owns row r, cols [16jc, 16jc+16)
    {
        const int r = tid >> 4, jc = tid & 15;
        const int c0 = jc * 16;
        unsigned long long acc[8];
        #pragma unroll
        for (int i = 0; i < 8; i++) acc[i] = 0ull;

        const float* m2p = g_M2 + c0;
        const float* ap = &s_lnx[r][0];
        #pragma unroll 2
        for (int k = 0; k < CDIM; k++) {
            float4 u0 = *(const float4*)(m2p + 0);
            float4 u1 = *(const float4*)(m2p + 4);
            float4 u2 = *(const float4*)(m2p + 8);
            float4 u3 = *(const float4*)(m2p + 12);
            m2p += CDIM;
            float a = ap[k];
            unsigned long long ad;
            PACK2(ad, a, a);
            FMA2(acc[0], ad, *(const unsigned long long*)&u0.x);
            FMA2(acc[1], ad, *(const unsigned long long*)&u0.z);
            FMA2(acc[2], ad, *(const unsigned long long*)&u1.x);
            FMA2(acc[3], ad, *(const unsigned long long*)&u1.z);
            FMA2(acc[4], ad, *(const unsigned long long*)&u2.x);
            FMA2(acc[5], ad, *(const unsigned long long*)&u2.z);
            FMA2(acc[6], ad, *(const unsigned long long*)&u3.x);
            FMA2(acc[7], ad, *(const unsigned long long*)&u3.z);
        }

        float gsum = 0.f;
        #pragma unroll
        for (int i = 0; i < 4; i++) {
            float4 bv = *(const float4*)(g_bv2 + c0 + i * 4);
            float2 p0 = unpack2(acc[i * 2 + 0]);
            float2 p1 = unpack2(acc[i * 2 + 1]);
            float4 wv = make_float4(p0.x + bv.x, p0.y + bv.y, p1.x + bv.z, p1.y + bv.w);
            *(float4*)&s_w[r][c0 + i * 4] = wv;
            gsum += wv.x + wv.y + wv.z + wv.w;
        }
        // reduce gsum over the 16 jc-lanes of each half-warp
        #pragma unroll
        for (int o = 8; o; o >>= 1) gsum += __shfl_xor_sync(0xffffffffu, gsum, o);
        if (jc == 0) s_G[r] = gsum;
    }
    __syncthreads();

    // ---------- Phase C: stream y, logits, softmax, z-weighted sum ----------
    const int n = tid >> 3, t8 = tid & 7;
    for (int r = 0; r < RB; r++) {
        const int row = row0 + r;
        const float* yr = y + ((size_t)row * NDIM + n) * CDIM;
        float S1 = 0.f, S2 = 0.f, S3 = 0.f;
        #pragma unroll
        for (int jj = 0; jj < 8; jj++) {
            const int col = jj * 32 + t8 * 4;
            float4 yv = __ldcs((const float4*)(yr + col));
            float4 w4 = *(const float4*)&s_w[r][col];
            S1 += yv.x + yv.y + yv.z + yv.w;
            S2 += yv.x*yv.x + yv.y*yv.y + yv.z*yv.z + yv.w*yv.w;
            S3 += yv.x*w4.x + yv.y*w4.y + yv.z*w4.z + yv.w*w4.w;
        }
        #pragma unroll
        for (int o = 4; o; o >>= 1) {
            S1 += __shfl_down_sync(0xffffffffu, S1, o);
            S2 += __shfl_down_sync(0xffffffffu, S2, o);
            S3 += __shfl_down_sync(0xffffffffu, S3, o);
        }
        if (t8 == 0) {
            float mu = S1 * (1.f / CDIM);
            float var = S2 * (1.f / CDIM) - mu * mu;
            float rs = rsqrtf(var + LN_EPS);
            s_dot[r & 1][n] = SCALE * (rs * (S3 - mu * s_G[r]) + s_bc[r]);
        }
        __syncthreads();
        if (tid < NDIM) {
            float v = s_dot[r & 1][tid];
            float m = v;
            #pragma unroll
            for (int o = 16; o; o >>= 1) m = fmaxf(m, __shfl_xor_sync(0xffffffffu, m, o));
            float e = expf(v - m);
            float zb = z[(size_t)row * NDIM + tid];
            float se = e, sez = e * zb;
            #pragma unroll
            for (int o = 16; o; o >>= 1) {
                se += __shfl_xor_sync(0xffffffffu, se, o);
                sez += __shfl_xor_sync(0xffffffffu, sez, o);
            }
            if (tid == 0) out[row] = sez / se;
        }
    }
}

// ---------------- launch ----------------
extern "C" void kernel_launch(void* const* d_in, const int* in_sizes, int n_in,
                              void* d_out, int out_size) {
    const float* x  = (const float*)d_in[0];
    const float* y  = (const float*)d_in[1];
    const float* z  = (const float*)d_in[2];
    const float* qg = (const float*)d_in[3];
    const float* qb = (const float*)d_in[4];
    const float* Wq = (const float*)d_in[5];
    const float* bq = (const float*)d_in[6];
    const float* kg = (const float*)d_in[7];
    const float* kb = (const float*)d_in[8];
    const float* Wk = (const float*)d_in[9];
    const float* bk = (const float*)d_in[10];
    float* out = (float*)d_out;

    prep_kernel<<<CDIM, 256>>>(Wq, Wk, bq, bk, kg, kb);
    prep2_kernel<<<1, 256>>>(qg, qb);
    fused_kernel<<<ROWS / RB, 256>>>(x, y, z, qg, qb, out);
}

// round 4
// speedup vs baseline: 3.3726x; 3.3726x over previous
#include <cuda_runtime.h>
#include <cuda_bf16.h>
#include <cstdint>

// Problem constants (fixed by setup_inputs)
#define BATCH 4
#define MDIM 4096
#define NDIM 32
#define CDIM 256
#define DDIM 128
#define ROWS (BATCH * MDIM)        // 16384
#define LN_EPS 1e-5f
#define SCALE 0.08838834764831845f // 1/sqrt(128)

// ---------------- scratch (device globals, no allocation) ----------------
__device__ __align__(16) float g_Mraw[CDIM * CDIM]; // Wq @ Wk^T
__device__ __align__(16) float g_M2[CDIM * CDIM];   // Mraw[c][c'] * k_gamma[c']
__device__ __align__(16) float g_bv[CDIM];          // Wk[c',:]·bq
__device__ __align__(16) float g_bv2[CDIM];         // k_gamma * bv
__device__ __align__(16) float g_rowvec[CDIM];      // mb[c] + u[c]
__device__ __align__(16) float g_e[CDIM];           // q_gamma ⊙ rowvec
__device__ float g_EF[2];                           // {E = Σe, F + const}
__device__ float2 g_stat[ROWS];                     // {mu, rs} per row of x
__device__ __align__(16) float g_w[ROWS * CDIM];    // per-row weight vectors
__device__ float g_Bc[ROWS];                        // per-row scalar bias

// ---------------- helpers ----------------
__device__ __forceinline__ float blockSum256(float v, float* s8) {
    #pragma unroll
    for (int o = 16; o; o >>= 1) v += __shfl_xor_sync(0xffffffffu, v, o);
    __syncthreads();
    if ((threadIdx.x & 31) == 0) s8[threadIdx.x >> 5] = v;
    __syncthreads();
    float tot = 0.f;
    #pragma unroll
    for (int i = 0; i < 8; i++) tot += s8[i];
    return tot;
}

#define FMA2(d, a, b) \
    asm("fma.rn.f32x2 %0, %1, %2, %0;" : "+l"(d) : "l"(a), "l"(b))
#define PACK2(out, lo, hi) \
    asm("mov.b64 %0, {%1, %2};" : "=l"(out) : "r"(__float_as_uint(lo)), "r"(__float_as_uint(hi)))

__device__ __forceinline__ float2 unpack2(unsigned long long v) {
    unsigned int lo, hi;
    asm("mov.b64 {%0, %1}, %2;" : "=r"(lo), "=r"(hi) : "l"(v));
    return make_float2(__uint_as_float(lo), __uint_as_float(hi));
}

// ---------------- K1a: Mraw = Wq(256x128) @ Wk^T(128x256), tiled, coalesced ----------------
__global__ void prepA_kernel(const float* __restrict__ Wq, const float* __restrict__ Wk) {
    __shared__ float As[32][68];   // [d][c]  (transposed on store)
    __shared__ float Bs[32][68];   // [d][c']
    const int bm = blockIdx.y * 64;
    const int bn = blockIdx.x * 64;
    const int tid = threadIdx.x;
    const int tx = tid & 15, ty = tid >> 4;
    const int r = tid >> 2, dq = tid & 3;   // staging: row r (0..63), d-octet dq

    float acc[4][4];
    #pragma unroll
    for (int i = 0; i < 4; i++)
        #pragma unroll
        for (int j = 0; j < 4; j++) acc[i][j] = 0.f;

    for (int k0 = 0; k0 < DDIM; k0 += 32) {
        // load 64x32 tiles of Wq and Wk, coalesced along d; store transposed
        float4 a0 = *(const float4*)(Wq + (size_t)(bm + r) * DDIM + k0 + dq * 8);
        float4 a1 = *(const float4*)(Wq + (size_t)(bm + r) * DDIM + k0 + dq * 8 + 4);
        float4 b0 = *(const float4*)(Wk + (size_t)(bn + r) * DDIM + k0 + dq * 8);
        float4 b1 = *(const float4*)(Wk + (size_t)(bn + r) * DDIM + k0 + dq * 8 + 4);
        As[dq * 8 + 0][r] = a0.x; As[dq * 8 + 1][r] = a0.y;
        As[dq * 8 + 2][r] = a0.z; As[dq * 8 + 3][r] = a0.w;
        As[dq * 8 + 4][r] = a1.x; As[dq * 8 + 5][r] = a1.y;
        As[dq * 8 + 6][r] = a1.z; As[dq * 8 + 7][r] = a1.w;
        Bs[dq * 8 + 0][r] = b0.x; Bs[dq * 8 + 1][r] = b0.y;
        Bs[dq * 8 + 2][r] = b0.z; Bs[dq * 8 + 3][r] = b0.w;
        Bs[dq * 8 + 4][r] = b1.x; Bs[dq * 8 + 5][r] = b1.y;
        Bs[dq * 8 + 6][r] = b1.z; Bs[dq * 8 + 7][r] = b1.w;
        __syncthreads();
        #pragma unroll
        for (int k = 0; k < 32; k++) {
            float4 a = *(const float4*)&As[k][ty * 4];
            float4 b = *(const float4*)&Bs[k][tx * 4];
            float ai[4] = {a.x, a.y, a.z, a.w};
            float bj[4] = {b.x, b.y, b.z, b.w};
            #pragma unroll
            for (int i = 0; i < 4; i++)
                #pragma unroll
                for (int j = 0; j < 4; j++) acc[i][j] += ai[i] * bj[j];
        }
        __syncthreads();
    }
    #pragma unroll
    for (int i = 0; i < 4; i++)
        *(float4*)(g_Mraw + (size_t)(bm + ty * 4 + i) * CDIM + bn + tx * 4) =
            make_float4(acc[i][0], acc[i][1], acc[i][2], acc[i][3]);
}

// ---------------- K1b: per-c derived vectors (coalesced) ----------------
__global__ void prepB_kernel(const float* __restrict__ Wq, const float* __restrict__ Wk,
                             const float* __restrict__ bq, const float* __restrict__ bk,
                             const float* __restrict__ kg, const float* __restrict__ kb) {
    const int c = blockIdx.x;      // 0..255
    const int t = threadIdx.x;     // 0..255
    __shared__ float s8[8];
    float mraw = g_Mraw[(size_t)c * CDIM + t];
    g_M2[(size_t)c * CDIM + t] = mraw * kg[t];
    float mb = blockSum256(mraw * kb[t], s8);
    float u  = blockSum256(t < DDIM ? Wq[(size_t)c * DDIM + t] * bk[t] : 0.f, s8);
    float bv = blockSum256(t < DDIM ? Wk[(size_t)c * DDIM + t] * bq[t] : 0.f, s8);
    if (t == 0) {
        g_rowvec[c] = mb + u;
        g_bv[c] = bv;
        g_bv2[c] = bv * kg[c];
    }
}

// ---------------- K1c: e, E, F(+const) ----------------
__global__ void prep2_kernel(const float* __restrict__ qg, const float* __restrict__ qb,
                             const float* __restrict__ bq, const float* __restrict__ bk,
                             const float* __restrict__ kb) {
    const int t = threadIdx.x;
    __shared__ float s8[8];
    float rv = g_rowvec[t];
    float e = qg[t] * rv;
    g_e[t] = e;
    float E = blockSum256(e, s8);
    float F = blockSum256(qb[t] * rv, s8);
    float cb = blockSum256(g_bv[t] * kb[t], s8);
    float bb = blockSum256(t < DDIM ? bq[t] * bk[t] : 0.f, s8);
    if (t == 0) { g_EF[0] = E; g_EF[1] = F + cb + bb; }
}

// ---------------- K2: per-row stats of x + Bc ----------------
__global__ void stats_kernel(const float* __restrict__ x) {
    const int row = blockIdx.x;
    const int t = threadIdx.x;
    __shared__ float s8[8];
    float xv = x[(size_t)row * CDIM + t];
    float s1 = blockSum256(xv, s8);
    float s2 = blockSum256(xv * xv, s8);
    float s3 = blockSum256(xv * g_e[t], s8);
    float mu = s1 * (1.f / CDIM);
    float var = s2 * (1.f / CDIM) - mu * mu;
    float rs = rsqrtf(var + LN_EPS);
    if (t == 0) {
        g_stat[row] = make_float2(mu, rs);
        g_Bc[row] = rs * (s3 - mu * g_EF[0]) + g_EF[1];
    }
}

// ---------------- K3: GEMM  w = LN(x)(16384x256) @ M2(256x256) + bv2 ----------------
// 64(M) x 128(N) tile, BK=16, 256 threads, 4x8 per thread, packed f32x2 FMAs.
__global__ void __launch_bounds__(256)
gemm_kernel(const float* __restrict__ x,
            const float* __restrict__ qg, const float* __restrict__ qb) {
    __shared__ __align__(16) float As[16][68];   // [k][m]
    __shared__ __align__(16) float Bs[16][132];  // [k][n]

    const int bm = blockIdx.y * 64;
    const int bn = blockIdx.x * 128;
    const int tid = threadIdx.x;
    const int tx = tid & 15;          // n-group: cols tx*4 and 64+tx*4
    const int ty = tid >> 4;          // m-group: rows ty*4..+3
    const int r0 = tid >> 2;          // A staging row 0..63
    const int aq = tid & 3;           // A staging k-quad
    const int kr = tid >> 4;          // B staging k-row 0..15
    const int cq = tid & 15;          // B staging col-octet

    const float2 st = g_stat[bm + r0];

    unsigned long long acc[4][4];
    #pragma unroll
    for (int i = 0; i < 4; i++)
        #pragma unroll
        for (int j = 0; j < 4; j++) acc[i][j] = 0ull;

    for (int k0 = 0; k0 < CDIM; k0 += 16) {
        // stage A with fused LayerNorm
        float4 gq = *(const float4*)(qg + k0 + aq * 4);
        float4 gb = *(const float4*)(qb + k0 + aq * 4);
        float4 xa = *(const float4*)(x + (size_t)(bm + r0) * CDIM + k0 + aq * 4);
        {
            float t0 = st.y * gq.x, t1 = st.y * gq.y, t2 = st.y * gq.z, t3 = st.y * gq.w;
            As[aq * 4 + 0][r0] = fmaf(xa.x, t0, gb.x - st.x * t0);
            As[aq * 4 + 1][r0] = fmaf(xa.y, t1, gb.y - st.x * t1);
            As[aq * 4 + 2][r0] = fmaf(xa.z, t2, gb.z - st.x * t2);
            As[aq * 4 + 3][r0] = fmaf(xa.w, t3, gb.w - st.x * t3);
        }
        // stage B (two float4 per thread)
        *(float4*)&Bs[kr][cq * 8] =
            *(const float4*)(g_M2 + (size_t)(k0 + kr) * CDIM + bn + cq * 8);
        *(float4*)&Bs[kr][cq * 8 + 4] =
            *(const float4*)(g_M2 + (size_t)(k0 + kr) * CDIM + bn + cq * 8 + 4);
        __syncthreads();

        #pragma unroll
        for (int k = 0; k < 16; k++) {
            float4 a = *(const float4*)&As[k][ty * 4];
            const unsigned long long* p0 = (const unsigned long long*)&Bs[k][tx * 4];
            const unsigned long long* p1 = (const unsigned long long*)&Bs[k][64 + tx * 4];
            unsigned long long b0 = p0[0], b1 = p0[1], b2 = p1[0], b3 = p1[1];
            float av[4] = {a.x, a.y, a.z, a.w};
            #pragma unroll
            for (int i = 0; i < 4; i++) {
                unsigned long long ad;
                PACK2(ad, av[i], av[i]);
                FMA2(acc[i][0], ad, b0);
                FMA2(acc[i][1], ad, b1);
                FMA2(acc[i][2], ad, b2);
                FMA2(acc[i][3], ad, b3);
            }
        }
        __syncthreads();
    }

    float4 bias0 = *(const float4*)(g_bv2 + bn + tx * 4);
    float4 bias1 = *(const float4*)(g_bv2 + bn + 64 + tx * 4);
    #pragma unroll
    for (int i = 0; i < 4; i++) {
        const int row = bm + ty * 4 + i;
        float2 p0 = unpack2(acc[i][0]);
        float2 p1 = unpack2(acc[i][1]);
        float2 p2 = unpack2(acc[i][2]);
        float2 p3 = unpack2(acc[i][3]);
        *(float4*)(g_w + (size_t)row * CDIM + bn + tx * 4) =
            make_float4(p0.x + bias0.x, p0.y + bias0.y, p1.x + bias0.z, p1.y + bias0.w);
        *(float4*)(g_w + (size_t)row * CDIM + bn + 64 + tx * 4) =
            make_float4(p2.x + bias1.x, p2.y + bias1.y, p3.x + bias1.z, p3.y + bias1.w);
    }
}

// ---------------- K4: main streaming pass over y + softmax + z-sum ----------------
__global__ void attn_kernel(const float* __restrict__ y, const float* __restrict__ z,
                            float* __restrict__ out) {
    const int row = blockIdx.x;    // b*M + m
    const int tid = threadIdx.x;   // 256 threads
    __shared__ __align__(16) float sw[CDIM];
    __shared__ float s8[8];
    __shared__ float sdot[NDIM];

    float wv = g_w[(size_t)row * CDIM + tid];
    sw[tid] = wv;
    float G = blockSum256(wv, s8);   // includes syncthreads -> sw visible

    const int n = tid >> 3, t8 = tid & 7;
    const float* yr = y + ((size_t)row * NDIM + n) * CDIM;
    float S1 = 0.f, S2 = 0.f, S3 = 0.f;
    #pragma unroll
    for (int j = 0; j < 8; j++) {
        const int col = j * 32 + t8 * 4;
        float4 yv = __ldcs((const float4*)(yr + col));
        float4 w4 = *(const float4*)(sw + col);
        S1 += yv.x + yv.y + yv.z + yv.w;
        S2 += yv.x * yv.x + yv.y * yv.y + yv.z * yv.z + yv.w * yv.w;
        S3 += yv.x * w4.x + yv.y * w4.y + yv.z * w4.z + yv.w * w4.w;
    }
    #pragma unroll
    for (int o = 4; o; o >>= 1) {
        S1 += __shfl_down_sync(0xffffffffu, S1, o);
        S2 += __shfl_down_sync(0xffffffffu, S2, o);
        S3 += __shfl_down_sync(0xffffffffu, S3, o);
    }
    if (t8 == 0) {
        float mu = S1 * (1.f / CDIM);
        float var = S2 * (1.f / CDIM) - mu * mu;
        float rs = rsqrtf(var + LN_EPS);
        sdot[n] = SCALE * (rs * (S3 - mu * G) + g_Bc[row]);
    }
    __syncthreads();
    if (tid < NDIM) {
        float v = sdot[tid];
        float m = v;
        #pragma unroll
        for (int o = 16; o; o >>= 1) m = fmaxf(m, __shfl_xor_sync(0xffffffffu, m, o));
        float e = expf(v - m);
        float zb = z[(size_t)row * NDIM + tid];
        float se = e, sez = e * zb;
        #pragma unroll
        for (int o = 16; o; o >>= 1) {
            se += __shfl_xor_sync(0xffffffffu, se, o);
            sez += __shfl_xor_sync(0xffffffffu, sez, o);
        }
        if (tid == 0) out[row] = sez / se;
    }
}

// ---------------- launch ----------------
extern "C" void kernel_launch(void* const* d_in, const int* in_sizes, int n_in,
                              void* d_out, int out_size) {
    const float* x  = (const float*)d_in[0];
    const float* y  = (const float*)d_in[1];
    const float* z  = (const float*)d_in[2];
    const float* qg = (const float*)d_in[3];
    const float* qb = (const float*)d_in[4];
    const float* Wq = (const float*)d_in[5];
    const float* bq = (const float*)d_in[6];
    const float* kg = (const float*)d_in[7];
    const float* kb = (const float*)d_in[8];
    const float* Wk = (const float*)d_in[9];
    const float* bk = (const float*)d_in[10];
    float* out = (float*)d_out;

    prepA_kernel<<<dim3(4, 4), 256>>>(Wq, Wk);
    prepB_kernel<<<CDIM, 256>>>(Wq, Wk, bq, bk, kg, kb);
    prep2_kernel<<<1, 256>>>(qg, qb, bq, bk, kb);
    stats_kernel<<<ROWS, 256>>>(x);
    gemm_kernel<<<dim3(2, 256), 256>>>(x, qg, qb);
    attn_kernel<<<ROWS, 256>>>(y, z, out);
}

// round 5
// speedup vs baseline: 3.6617x; 1.0857x over previous
#include <cuda_runtime.h>
#include <cuda_bf16.h>
#include <cstdint>

// Problem constants (fixed by setup_inputs)
#define BATCH 4
#define MDIM 4096
#define NDIM 32
#define CDIM 256
#define DDIM 128
#define ROWS (BATCH * MDIM)        // 16384
#define LN_EPS 1e-5f
#define SCALE 0.08838834764831845f // 1/sqrt(128)

// ---------------- scratch (device globals, no allocation) ----------------
__device__ __align__(16) float g_Mraw[CDIM * CDIM]; // Wq @ Wk^T
__device__ __align__(16) float g_M2[CDIM * CDIM];   // Mraw[c][c'] * k_gamma[c']
__device__ __align__(16) float g_bv[CDIM];          // Wk[c',:]·bq
__device__ __align__(16) float g_bv2[CDIM];         // k_gamma * bv
__device__ __align__(16) float g_rowvec[CDIM];      // mb[c] + u[c]
__device__ __align__(16) float g_e[CDIM];           // q_gamma ⊙ rowvec
__device__ float g_EF[2];                           // {E = Σe, F + const}
__device__ float2 g_stat[ROWS];                     // {mu, rs} per row of x
__device__ __align__(16) float g_w[ROWS * CDIM];    // per-row weight vectors
__device__ float g_Bc[ROWS];                        // per-row scalar bias

// ---------------- helpers ----------------
__device__ __forceinline__ float blockSum256(float v, float* s8) {
    #pragma unroll
    for (int o = 16; o; o >>= 1) v += __shfl_xor_sync(0xffffffffu, v, o);
    __syncthreads();
    if ((threadIdx.x & 31) == 0) s8[threadIdx.x >> 5] = v;
    __syncthreads();
    float tot = 0.f;
    #pragma unroll
    for (int i = 0; i < 8; i++) tot += s8[i];
    return tot;
}

#define FMA2(d, a, b) \
    asm("fma.rn.f32x2 %0, %1, %2, %0;" : "+l"(d) : "l"(a), "l"(b))
#define PACK2(out, lo, hi) \
    asm("mov.b64 %0, {%1, %2};" : "=l"(out) : "r"(__float_as_uint(lo)), "r"(__float_as_uint(hi)))

__device__ __forceinline__ float2 unpack2(unsigned long long v) {
    unsigned int lo, hi;
    asm("mov.b64 {%0, %1}, %2;" : "=r"(lo), "=r"(hi) : "l"(v));
    return make_float2(__uint_as_float(lo), __uint_as_float(hi));
}

// ---------------- K1a: Mraw = Wq(256x128) @ Wk^T(128x256), tiled, coalesced ----------------
__global__ void prepA_kernel(const float* __restrict__ Wq, const float* __restrict__ Wk) {
    __shared__ float As[32][68];   // [d][c]  (transposed on store)
    __shared__ float Bs[32][68];   // [d][c']
    const int bm = blockIdx.y * 64;
    const int bn = blockIdx.x * 64;
    const int tid = threadIdx.x;
    const int tx = tid & 15, ty = tid >> 4;
    const int r = tid >> 2, dq = tid & 3;

    float acc[4][4];
    #pragma unroll
    for (int i = 0; i < 4; i++)
        #pragma unroll
        for (int j = 0; j < 4; j++) acc[i][j] = 0.f;

    for (int k0 = 0; k0 < DDIM; k0 += 32) {
        float4 a0 = *(const float4*)(Wq + (size_t)(bm + r) * DDIM + k0 + dq * 8);
        float4 a1 = *(const float4*)(Wq + (size_t)(bm + r) * DDIM + k0 + dq * 8 + 4);
        float4 b0 = *(const float4*)(Wk + (size_t)(bn + r) * DDIM + k0 + dq * 8);
        float4 b1 = *(const float4*)(Wk + (size_t)(bn + r) * DDIM + k0 + dq * 8 + 4);
        As[dq * 8 + 0][r] = a0.x; As[dq * 8 + 1][r] = a0.y;
        As[dq * 8 + 2][r] = a0.z; As[dq * 8 + 3][r] = a0.w;
        As[dq * 8 + 4][r] = a1.x; As[dq * 8 + 5][r] = a1.y;
        As[dq * 8 + 6][r] = a1.z; As[dq * 8 + 7][r] = a1.w;
        Bs[dq * 8 + 0][r] = b0.x; Bs[dq * 8 + 1][r] = b0.y;
        Bs[dq * 8 + 2][r] = b0.z; Bs[dq * 8 + 3][r] = b0.w;
        Bs[dq * 8 + 4][r] = b1.x; Bs[dq * 8 + 5][r] = b1.y;
        Bs[dq * 8 + 6][r] = b1.z; Bs[dq * 8 + 7][r] = b1.w;
        __syncthreads();
        #pragma unroll
        for (int k = 0; k < 32; k++) {
            float4 a = *(const float4*)&As[k][ty * 4];
            float4 b = *(const float4*)&Bs[k][tx * 4];
            float ai[4] = {a.x, a.y, a.z, a.w};
            float bj[4] = {b.x, b.y, b.z, b.w};
            #pragma unroll
            for (int i = 0; i < 4; i++)
                #pragma unroll
                for (int j = 0; j < 4; j++) acc[i][j] += ai[i] * bj[j];
        }
        __syncthreads();
    }
    #pragma unroll
    for (int i = 0; i < 4; i++)
        *(float4*)(g_Mraw + (size_t)(bm + ty * 4 + i) * CDIM + bn + tx * 4) =
            make_float4(acc[i][0], acc[i][1], acc[i][2], acc[i][3]);
}

// ---------------- K1b: per-c derived vectors (coalesced) ----------------
__global__ void prepB_kernel(const float* __restrict__ Wq, const float* __restrict__ Wk,
                             const float* __restrict__ bq, const float* __restrict__ bk,
                             const float* __restrict__ kg, const float* __restrict__ kb) {
    const int c = blockIdx.x;      // 0..255
    const int t = threadIdx.x;     // 0..255
    __shared__ float s8[8];
    float mraw = g_Mraw[(size_t)c * CDIM + t];
    g_M2[(size_t)c * CDIM + t] = mraw * kg[t];
    float mb = blockSum256(mraw * kb[t], s8);
    float u  = blockSum256(t < DDIM ? Wq[(size_t)c * DDIM + t] * bk[t] : 0.f, s8);
    float bv = blockSum256(t < DDIM ? Wk[(size_t)c * DDIM + t] * bq[t] : 0.f, s8);
    if (t == 0) {
        g_rowvec[c] = mb + u;
        g_bv[c] = bv;
        g_bv2[c] = bv * kg[c];
    }
}

// ---------------- K1c: e, E, F(+const) ----------------
__global__ void prep2_kernel(const float* __restrict__ qg, const float* __restrict__ qb,
                             const float* __restrict__ bq, const float* __restrict__ bk,
                             const float* __restrict__ kb) {
    const int t = threadIdx.x;
    __shared__ float s8[8];
    float rv = g_rowvec[t];
    float e = qg[t] * rv;
    g_e[t] = e;
    float E = blockSum256(e, s8);
    float F = blockSum256(qb[t] * rv, s8);
    float cb = blockSum256(g_bv[t] * kb[t], s8);
    float bb = blockSum256(t < DDIM ? bq[t] * bk[t] : 0.f, s8);
    if (t == 0) { g_EF[0] = E; g_EF[1] = F + cb + bb; }
}

// ---------------- K2: per-row stats of x + Bc (warp per row, 8 rows/block) ----------------
__global__ void __launch_bounds__(256)
stats_kernel(const float* __restrict__ x) {
    const int w = threadIdx.x >> 5, l = threadIdx.x & 31;
    const int row = blockIdx.x * 8 + w;
    const float* xr = x + (size_t)row * CDIM + l * 8;

    float4 xa = *(const float4*)(xr);
    float4 xb = *(const float4*)(xr + 4);
    float4 e0 = *(const float4*)(g_e + l * 8);
    float4 e1 = *(const float4*)(g_e + l * 8 + 4);

    float s1 = xa.x + xa.y + xa.z + xa.w + xb.x + xb.y + xb.z + xb.w;
    float s2 = xa.x*xa.x + xa.y*xa.y + xa.z*xa.z + xa.w*xa.w
             + xb.x*xb.x + xb.y*xb.y + xb.z*xb.z + xb.w*xb.w;
    float s3 = xa.x*e0.x + xa.y*e0.y + xa.z*e0.z + xa.w*e0.w
             + xb.x*e1.x + xb.y*e1.y + xb.z*e1.z + xb.w*e1.w;
    #pragma unroll
    for (int o = 16; o; o >>= 1) {
        s1 += __shfl_xor_sync(0xffffffffu, s1, o);
        s2 += __shfl_xor_sync(0xffffffffu, s2, o);
        s3 += __shfl_xor_sync(0xffffffffu, s3, o);
    }
    if (l == 0) {
        float mu = s1 * (1.f / CDIM);
        float var = s2 * (1.f / CDIM) - mu * mu;
        float rs = rsqrtf(var + LN_EPS);
        g_stat[row] = make_float2(mu, rs);
        g_Bc[row] = rs * (s3 - mu * g_EF[0]) + g_EF[1];
    }
}

// ---------------- K3: GEMM  w = LN(x)(16384x256) @ M2(256x256) + bv2 ----------------
// 64(M) x 128(N) tile, BK=16, 256 threads, 4x8 per thread, packed f32x2 FMAs,
// register-prefetch double buffering.
__global__ void __launch_bounds__(256)
gemm_kernel(const float* __restrict__ x,
            const float* __restrict__ qg, const float* __restrict__ qb) {
    __shared__ __align__(16) float As[16][68];   // [k][m]
    __shared__ __align__(16) float Bs[16][132];  // [k][n]

    const int bm = blockIdx.y * 64;
    const int bn = blockIdx.x * 128;
    const int tid = threadIdx.x;
    const int tx = tid & 15;          // n-group: cols tx*4 and 64+tx*4
    const int ty = tid >> 4;          // m-group: rows ty*4..+3
    const int r0 = tid >> 2;          // A staging row 0..63
    const int aq = tid & 3;           // A staging k-quad
    const int kr = tid >> 4;          // B staging k-row 0..15
    const int cq = tid & 15;          // B staging col-octet

    const float2 st = g_stat[bm + r0];

    const float* xp  = x + (size_t)(bm + r0) * CDIM + aq * 4;
    const float* qgp = qg + aq * 4;
    const float* qbp = qb + aq * 4;
    const float* bpg = g_M2 + (size_t)kr * CDIM + bn + cq * 8;

    unsigned long long acc[4][4];
    #pragma unroll
    for (int i = 0; i < 4; i++)
        #pragma unroll
        for (int j = 0; j < 4; j++) acc[i][j] = 0ull;

    // prologue: prefetch tile 0
    float4 xa  = *(const float4*)(xp);
    float4 gq  = *(const float4*)(qgp);
    float4 gb  = *(const float4*)(qbp);
    float4 b0v = *(const float4*)(bpg);
    float4 b1v = *(const float4*)(bpg + 4);

    for (int k0 = 0; k0 < CDIM; k0 += 16) {
        // stage prefetched regs into smem (LN fused for A)
        {
            float t0 = st.y * gq.x, t1 = st.y * gq.y, t2 = st.y * gq.z, t3 = st.y * gq.w;
            As[aq * 4 + 0][r0] = fmaf(xa.x, t0, gb.x - st.x * t0);
            As[aq * 4 + 1][r0] = fmaf(xa.y, t1, gb.y - st.x * t1);
            As[aq * 4 + 2][r0] = fmaf(xa.z, t2, gb.z - st.x * t2);
            As[aq * 4 + 3][r0] = fmaf(xa.w, t3, gb.w - st.x * t3);
        }
        *(float4*)&Bs[kr][cq * 8]     = b0v;
        *(float4*)&Bs[kr][cq * 8 + 4] = b1v;
        __syncthreads();

        // prefetch next tile (overlaps with compute below)
        if (k0 + 16 < CDIM) {
            xa  = *(const float4*)(xp + k0 + 16);
            gq  = *(const float4*)(qgp + k0 + 16);
            gb  = *(const float4*)(qbp + k0 + 16);
            b0v = *(const float4*)(bpg + (size_t)(k0 + 16) * CDIM);
            b1v = *(const float4*)(bpg + (size_t)(k0 + 16) * CDIM + 4);
        }

        #pragma unroll
        for (int k = 0; k < 16; k++) {
            float4 a = *(const float4*)&As[k][ty * 4];
            const unsigned long long* p0 = (const unsigned long long*)&Bs[k][tx * 4];
            const unsigned long long* p1 = (const unsigned long long*)&Bs[k][64 + tx * 4];
            unsigned long long b0 = p0[0], b1 = p0[1], b2 = p1[0], b3 = p1[1];
            float av[4] = {a.x, a.y, a.z, a.w};
            #pragma unroll
            for (int i = 0; i < 4; i++) {
                unsigned long long ad;
                PACK2(ad, av[i], av[i]);
                FMA2(acc[i][0], ad, b0);
                FMA2(acc[i][1], ad, b1);
                FMA2(acc[i][2], ad, b2);
                FMA2(acc[i][3], ad, b3);
            }
        }
        __syncthreads();
    }

    float4 bias0 = *(const float4*)(g_bv2 + bn + tx * 4);
    float4 bias1 = *(const float4*)(g_bv2 + bn + 64 + tx * 4);
    #pragma unroll
    for (int i = 0; i < 4; i++) {
        const int row = bm + ty * 4 + i;
        float2 p0 = unpack2(acc[i][0]);
        float2 p1 = unpack2(acc[i][1]);
        float2 p2 = unpack2(acc[i][2]);
        float2 p3 = unpack2(acc[i][3]);
        *(float4*)(g_w + (size_t)row * CDIM + bn + tx * 4) =
            make_float4(p0.x + bias0.x, p0.y + bias0.y, p1.x + bias0.z, p1.y + bias0.w);
        *(float4*)(g_w + (size_t)row * CDIM + bn + 64 + tx * 4) =
            make_float4(p2.x + bias1.x, p2.y + bias1.y, p3.x + bias1.z, p3.y + bias1.w);
    }
}

// ---------------- K4: main streaming pass over y + softmax + z-sum ----------------
__global__ void attn_kernel(const float* __restrict__ y, const float* __restrict__ z,
                            float* __restrict__ out) {
    const int row = blockIdx.x;    // b*M + m
    const int tid = threadIdx.x;   // 256 threads
    __shared__ __align__(16) float sw[CDIM];
    __shared__ float s8[8];
    __shared__ float sdot[NDIM];

    float wv = g_w[(size_t)row * CDIM + tid];
    sw[tid] = wv;
    float G = blockSum256(wv, s8);   // includes syncthreads -> sw visible

    const int n = tid >> 3, t8 = tid & 7;
    const float* yr = y + ((size_t)row * NDIM + n) * CDIM;
    float S1 = 0.f, S2 = 0.f, S3 = 0.f;
    #pragma unroll
    for (int j = 0; j < 8; j++) {
        const int col = j * 32 + t8 * 4;
        float4 yv = __ldcs((const float4*)(yr + col));
        float4 w4 = *(const float4*)(sw + col);
        S1 += yv.x + yv.y + yv.z + yv.w;
        S2 += yv.x * yv.x + yv.y * yv.y + yv.z * yv.z + yv.w * yv.w;
        S3 += yv.x * w4.x + yv.y * w4.y + yv.z * w4.z + yv.w * w4.w;
    }
    #pragma unroll
    for (int o = 4; o; o >>= 1) {
        S1 += __shfl_down_sync(0xffffffffu, S1, o);
        S2 += __shfl_down_sync(0xffffffffu, S2, o);
        S3 += __shfl_down_sync(0xffffffffu, S3, o);
    }
    if (t8 == 0) {
        float mu = S1 * (1.f / CDIM);
        float var = S2 * (1.f / CDIM) - mu * mu;
        float rs = rsqrtf(var + LN_EPS);
        sdot[n] = SCALE * (rs * (S3 - mu * G) + g_Bc[row]);
    }
    __syncthreads();
    if (tid < NDIM) {
        float v = sdot[tid];
        float m = v;
        #pragma unroll
        for (int o = 16; o; o >>= 1) m = fmaxf(m, __shfl_xor_sync(0xffffffffu, m, o));
        float e = expf(v - m);
        float zb = z[(size_t)row * NDIM + tid];
        float se = e, sez = e * zb;
        #pragma unroll
        for (int o = 16; o; o >>= 1) {
            se += __shfl_xor_sync(0xffffffffu, se, o);
            sez += __shfl_xor_sync(0xffffffffu, sez, o);
        }
        if (tid == 0) out[row] = sez / se;
    }
}

// ---------------- launch ----------------
extern "C" void kernel_launch(void* const* d_in, const int* in_sizes, int n_in,
                              void* d_out, int out_size) {
    const float* x  = (const float*)d_in[0];
    const float* y  = (const float*)d_in[1];
    const float* z  = (const float*)d_in[2];
    const float* qg = (const float*)d_in[3];
    const float* qb = (const float*)d_in[4];
    const float* Wq = (const float*)d_in[5];
    const float* bq = (const float*)d_in[6];
    const float* kg = (const float*)d_in[7];
    const float* kb = (const float*)d_in[8];
    const float* Wk = (const float*)d_in[9];
    const float* bk = (const float*)d_in[10];
    float* out = (float*)d_out;

    prepA_kernel<<<dim3(4, 4), 256>>>(Wq, Wk);
    prepB_kernel<<<CDIM, 256>>>(Wq, Wk, bq, bk, kg, kb);
    prep2_kernel<<<1, 256>>>(qg, qb, bq, bk, kb);
    stats_kernel<<<ROWS / 8, 256>>>(x);
    gemm_kernel<<<dim3(2, 256), 256>>>(x, qg, qb);
    attn_kernel<<<ROWS, 256>>>(y, z, out);
}